// round 4
// baseline (speedup 1.0000x reference)
#include <cuda_runtime.h>

// (4,4,3,192,192) fp32 -> (4,4,2,192,192): per-patch KDE entropies (R=3, h=0.1).
#define SFN 4
#define WW  192
#define HW  (192 * 192)

// H = log(9) + (C/2)*ln(2*pi*h^2) - (1/9)*sum_i ln(s_i)
#define CM     (-1.9537151021f)   // log9 + 1.5*ln(2*pi*0.01)  (C=3)
#define CJ     (-6.1046547815f)   // log9 + 3.0*ln(2*pi*0.01)  (C=6)
#define LN2_9  (0.0770163534f)    // ln(2)/9
#define PSC    (8.4932183f)       // sqrt(50*log2(e)): exp(-50*d2) = ex2(-|d'|^2)

#define ONE_ONE 0x3F8000003F800000ULL

typedef unsigned long long u64;

static __device__ __forceinline__ float fast_ex2(float x)
{ float r; asm("ex2.approx.ftz.f32 %0, %1;" : "=f"(r) : "f"(x)); return r; }

static __device__ __forceinline__ float fast_lg2(float x)
{ float r; asm("lg2.approx.f32 %0, %1;" : "=f"(r) : "f"(x)); return r; }

static __device__ __forceinline__ u64 packf2(float lo, float hi)
{ u64 r; asm("mov.b64 %0, {%1, %2};" : "=l"(r) : "f"(lo), "f"(hi)); return r; }

static __device__ __forceinline__ void unpackf2(float& lo, float& hi, u64 v)
{ asm("mov.b64 {%0, %1}, %2;" : "=f"(lo), "=f"(hi) : "l"(v)); }

static __device__ __forceinline__ u64 addf2(u64 a, u64 b)
{ u64 r; asm("add.rn.f32x2 %0, %1, %2;" : "=l"(r) : "l"(a), "l"(b)); return r; }

static __device__ __forceinline__ u64 mulf2(u64 a, u64 b)
{ u64 r; asm("mul.rn.f32x2 %0, %1, %2;" : "=l"(r) : "l"(a), "l"(b)); return r; }

// Load 4 rows x 3 cols x 3 channels, pre-scaled by PSC. Pixel idx = r*3+c.
static __device__ __forceinline__ void loadpx(const float* __restrict__ b, float p[12][3])
{
    #pragma unroll
    for (int c = 0; c < 3; ++c) {
        const float* bc = b + c * HW;
        #pragma unroll
        for (int r = 0; r < 4; ++r)
            #pragma unroll
            for (int cc = 0; cc < 3; ++cc)
                p[r * 3 + cc][c] = bc[r * WW + cc] * PSC;
    }
}

static __device__ __forceinline__ float prod9(const float s[9])
{
    return ((s[0] * s[1]) * (s[2] * s[3])) *
           ((s[4] * s[5]) * (s[6] * s[7])) * s[8];
}

static __device__ __forceinline__ u64 prod9p(const u64 a[9])
{
    u64 p = mulf2(mulf2(mulf2(a[0], a[1]), mulf2(a[2], a[3])),
                  mulf2(mulf2(a[4], a[5]), mulf2(a[6], a[7])));
    return mulf2(p, a[8]);
}

// Squared distance -> ex2 argument (pixels pre-scaled)
static __device__ __forceinline__ float pair_nt(const float* pa, const float* pb)
{
    float d0 = pa[0] - pb[0];
    float d1 = pa[1] - pb[1];
    float d2 = pa[2] - pb[2];
    float nt = -(d0 * d0);
    nt = fmaf(-d1, d1, nt);
    nt = fmaf(-d2, d2, nt);
    return nt;
}

// Zero one (row, col) position across all 8 output channels (cold border path)
static __device__ __forceinline__ void zero8(float* ob, int ofs)
{
    #pragma unroll
    for (int q = 0; q < 8; ++q) ob[q * HW + ofs] = 0.0f;
}

__global__ void __launch_bounds__(128, 3)
je2_kernel(const float* __restrict__ in, float* __restrict__ out)
{
    int x  = blockIdx.x * 32 + threadIdx.x;  // patch col, 0..189 valid
    int yy = blockIdx.y * 4 + threadIdx.y;   // patch-row pair, 0..94 valid
    int n  = blockIdx.z;

    if (x >= 190 || yy >= 95) return;

    float* ob = out + (size_t)n * 8 * HW;
    int y0 = yy * 2;                 // top patch row; bottom = y0+1
    int r1 = y0 + 1, r2 = y0 + 2;    // output rows of the two patches
    int oc = x + 1;                  // output col

    // ---- border zeroing (out is poisoned; the 1-px ring must be 0) ----
    if (x == 0) {
        zero8(ob, r1 * WW);
        zero8(ob, r2 * WW);
        if (yy == 0)  zero8(ob, 0);
        if (yy == 94) zero8(ob, 191 * WW);
    }
    if (x == 189) {
        zero8(ob, r1 * WW + 191);
        zero8(ob, r2 * WW + 191);
        if (yy == 0)  zero8(ob, 191);
        if (yy == 94) zero8(ob, 191 * WW + 191);
    }
    if (yy == 0)  zero8(ob, oc);
    if (yy == 94) zero8(ob, 191 * WW + oc);

    const float* ib = in + (size_t)n * (SFN * 3) * HW + y0 * WW + x;

    // 57 distinct pixel pairs in the 4x3 region (|dr| <= 2), persistent exps
    float e[57];

    // ================= frame 0: marginals only, seed e[] =================
    {
        float px[12][3];
        loadpx(ib, px);
        float sT[9], sB[9];
        #pragma unroll
        for (int i = 0; i < 9; ++i) { sT[i] = 1.0f; sB[i] = 1.0f; }
        int k = 0;
        #pragma unroll
        for (int a = 0; a < 12; ++a) {
            #pragma unroll
            for (int b = a + 1; b < 12; ++b) {
                if ((b / 3) - (a / 3) > 2) continue;   // compile-time pruned
                float ee = fast_ex2(pair_nt(px[a], px[b]));
                e[k] = ee;
                if (b < 9)  { sT[a] += ee; sT[b] += ee; }          // top patch: rows 0..2
                if (a >= 3) { sB[a - 3] += ee; sB[b - 3] += ee; }  // bottom: rows 1..3
                ++k;
            }
        }
        ob[r1*WW + oc] = CM - LN2_9 * fast_lg2(prod9(sT));   // ch 0
        ob[r2*WW + oc] = CM - LN2_9 * fast_lg2(prod9(sB));
    }

    // ====== frames 1,2: packed (marg_sf, joint_{sf-1}) accumulators ======
    #pragma unroll
    for (int sf = 1; sf <= 2; ++sf) {
        float px[12][3];
        loadpx(ib + sf * (3 * HW), px);
        u64 aT[9], aB[9];
        #pragma unroll
        for (int i = 0; i < 9; ++i) { aT[i] = ONE_ONE; aB[i] = ONE_ONE; }
        int k = 0;
        #pragma unroll
        for (int a = 0; a < 12; ++a) {
            #pragma unroll
            for (int b = a + 1; b < 12; ++b) {
                if ((b / 3) - (a / 3) > 2) continue;
                float ee = fast_ex2(pair_nt(px[a], px[b]));
                float ej = e[k] * ee;          // joint exp = product of frame exps
                e[k] = ee;
                u64 ad = packf2(ee, ej);
                if (b < 9)  { aT[a] = addf2(aT[a], ad); aT[b] = addf2(aT[b], ad); }
                if (a >= 3) { aB[a-3] = addf2(aB[a-3], ad); aB[b-3] = addf2(aB[b-3], ad); }
                ++k;
            }
        }
        float pm, pj;
        unpackf2(pm, pj, prod9p(aT));
        ob[(2*sf)*HW   + r1*WW + oc] = CM - LN2_9 * fast_lg2(pm);
        ob[(2*sf-1)*HW + r1*WW + oc] = CJ - LN2_9 * fast_lg2(pj);
        unpackf2(pm, pj, prod9p(aB));
        ob[(2*sf)*HW   + r2*WW + oc] = CM - LN2_9 * fast_lg2(pm);
        ob[(2*sf-1)*HW + r2*WW + oc] = CJ - LN2_9 * fast_lg2(pj);
    }

    // == frame 3: scalar marg3 + packed (joint23, joint33=self-pair) ==
    {
        float px[12][3];
        loadpx(ib + 3 * (3 * HW), px);
        float sT[9], sB[9];
        u64 jT[9], jB[9];
        #pragma unroll
        for (int i = 0; i < 9; ++i) {
            sT[i] = 1.0f; sB[i] = 1.0f; jT[i] = ONE_ONE; jB[i] = ONE_ONE;
        }
        int k = 0;
        #pragma unroll
        for (int a = 0; a < 12; ++a) {
            #pragma unroll
            for (int b = a + 1; b < 12; ++b) {
                if ((b / 3) - (a / 3) > 2) continue;
                float ee  = fast_ex2(pair_nt(px[a], px[b]));
                float e23 = e[k] * ee;     // joint frame2-frame3
                float e33 = ee * ee;       // last frame paired with itself
                u64 jd = packf2(e23, e33);
                if (b < 9)  { sT[a] += ee; sT[b] += ee;
                              jT[a] = addf2(jT[a], jd); jT[b] = addf2(jT[b], jd); }
                if (a >= 3) { sB[a-3] += ee; sB[b-3] += ee;
                              jB[a-3] = addf2(jB[a-3], jd); jB[b-3] = addf2(jB[b-3], jd); }
                ++k;
            }
        }
        float p23, p33;
        ob[6*HW + r1*WW + oc] = CM - LN2_9 * fast_lg2(prod9(sT));
        unpackf2(p23, p33, prod9p(jT));
        ob[5*HW + r1*WW + oc] = CJ - LN2_9 * fast_lg2(p23);
        ob[7*HW + r1*WW + oc] = CJ - LN2_9 * fast_lg2(p33);
        ob[6*HW + r2*WW + oc] = CM - LN2_9 * fast_lg2(prod9(sB));
        unpackf2(p23, p33, prod9p(jB));
        ob[5*HW + r2*WW + oc] = CJ - LN2_9 * fast_lg2(p23);
        ob[7*HW + r2*WW + oc] = CJ - LN2_9 * fast_lg2(p33);
    }
}

extern "C" void kernel_launch(void* const* d_in, const int* in_sizes, int n_in,
                              void* d_out, int out_size)
{
    dim3 blk(32, 4, 1);
    dim3 grd(6, 24, 4);   // x: 190 patch cols, y: 95 row-pairs, z: batch
    je2_kernel<<<grd, blk>>>((const float*)d_in[0], (float*)d_out);
}

// round 5
// speedup vs baseline: 5.3472x; 5.3472x over previous
#include <cuda_runtime.h>

// (4,4,3,192,192) fp32 -> (4,4,2,192,192): per-patch KDE entropies (R=3, h=0.1).
// Lane-split design: 4 consecutive lanes handle the 4 frames of one patch.
// Joint entropy uses exp(-50*(d2_a + d2_b)) = e_a * e_b; the neighbor frame's
// exps arrive via warp shuffle (lane+1), last frame pairs with itself.

#define WW  192
#define HW  (192 * 192)

#define CM     (-1.9537149f)      // log9 + 1.5*ln(2*pi*0.01)  (C=3 marginal)
#define CJ     (-6.1046541f)      // log9 + 3.0*ln(2*pi*0.01)  (C=6 joint)
#define LN2_9  (0.0770163534f)    // ln(2)/9
#define PSC    (8.4932200f)       // sqrt(50*log2(e)): exp(-50*d2)=ex2(-|p'|^2)

static __device__ __forceinline__ float fast_ex2(float x)
{ float r; asm("ex2.approx.ftz.f32 %0, %1;" : "=f"(r) : "f"(x)); return r; }

static __device__ __forceinline__ float fast_lg2(float x)
{ float r; asm("lg2.approx.f32 %0, %1;" : "=f"(r) : "f"(x)); return r; }

static __device__ __forceinline__ float prod9(const float s[9])
{
    return ((s[0] * s[1]) * (s[2] * s[3])) *
           ((s[4] * s[5]) * (s[6] * s[7])) * s[8];
}

__global__ void __launch_bounds__(128)
je_lane_kernel(const float* __restrict__ in, float* __restrict__ out)
{
    int lane = threadIdx.x & 31;
    int warp = threadIdx.x >> 5;
    int sf   = lane & 3;          // frame handled by this lane
    int sub  = lane >> 2;         // patch slot within warp (8 patches/warp)

    int x = blockIdx.x * 32 + warp * 8 + sub;   // patch col 0..191 (valid <190)
    int y = blockIdx.y;                         // patch row 0..189
    int n = blockIdx.z;

    bool valid = (x < 190);
    int  xc    = valid ? x : 189;   // clamp so edge lanes still shuffle safely

    const float* ib = in + ((size_t)(n * 4 + sf) * 3) * HW + y * WW + xc;

    // ---- load the 3x3x3 patch of this frame, pre-scaled ----
    float px[9][3];
    #pragma unroll
    for (int c = 0; c < 3; ++c) {
        const float* bc = ib + c * HW;
        #pragma unroll
        for (int dy = 0; dy < 3; ++dy)
            #pragma unroll
            for (int dx = 0; dx < 3; ++dx)
                px[dy * 3 + dx][c] = bc[dy * WW + dx] * PSC;
    }

    // ---- 36 pairwise exponentials + marginal row sums ----
    float e[36];
    float s[9];
    #pragma unroll
    for (int i = 0; i < 9; ++i) s[i] = 1.0f;    // diagonal exp(0)
    {
        int k = 0;
        #pragma unroll
        for (int i = 0; i < 9; ++i)
            #pragma unroll
            for (int j = i + 1; j < 9; ++j) {
                float d0 = px[i][0] - px[j][0];
                float d1 = px[i][1] - px[j][1];
                float d2 = px[i][2] - px[j][2];
                float nt = -(d0 * d0);
                nt = fmaf(-d1, d1, nt);
                nt = fmaf(-d2, d2, nt);
                float ee = fast_ex2(nt);
                e[k] = ee;
                s[i] += ee;
                s[j] += ee;
                ++k;
            }
    }
    float hm = CM - LN2_9 * fast_lg2(prod9(s));

    // ---- joint with next frame: e_joint = e_sf * e_{sf+1} (sf=3: self) ----
    int src = (sf == 3) ? lane : (lane + 1);
    float sj[9];
    #pragma unroll
    for (int i = 0; i < 9; ++i) sj[i] = 1.0f;
    {
        int k = 0;
        #pragma unroll
        for (int i = 0; i < 9; ++i)
            #pragma unroll
            for (int j = i + 1; j < 9; ++j) {
                float en = __shfl_sync(0xffffffffu, e[k], src);
                float ej = e[k] * en;
                sj[i] += ej;
                sj[j] += ej;
                ++k;
            }
    }
    float hj = CJ - LN2_9 * fast_lg2(prod9(sj));

    // ---- stores (this thread owns channels 2*sf and 2*sf+1 of batch n) ----
    if (valid) {
        float* ob = out + ((size_t)(n * 4 + sf) * 2) * HW;
        int oofs = (y + 1) * WW + (x + 1);
        ob[oofs]      = hm;
        ob[HW + oofs] = hj;

        // border zeroing for the 1-px ring (output is poisoned 0xAA)
        if (y == 0)   { ob[x + 1] = 0.0f;            ob[HW + x + 1] = 0.0f; }
        if (y == 189) { ob[191 * WW + x + 1] = 0.0f; ob[HW + 191 * WW + x + 1] = 0.0f; }
        if (x == 0) {
            ob[(y + 1) * WW] = 0.0f;      ob[HW + (y + 1) * WW] = 0.0f;
            if (y == 0)   { ob[0] = 0.0f;            ob[HW] = 0.0f; }
            if (y == 189) { ob[191 * WW] = 0.0f;     ob[HW + 191 * WW] = 0.0f; }
        }
        if (x == 189) {
            ob[(y + 1) * WW + 191] = 0.0f; ob[HW + (y + 1) * WW + 191] = 0.0f;
            if (y == 0)   { ob[191] = 0.0f;          ob[HW + 191] = 0.0f; }
            if (y == 189) { ob[191 * WW + 191] = 0.0f; ob[HW + 191 * WW + 191] = 0.0f; }
        }
    }
}

extern "C" void kernel_launch(void* const* d_in, const int* in_sizes, int n_in,
                              void* d_out, int out_size)
{
    dim3 blk(128, 1, 1);
    dim3 grd(6, 190, 4);   // 6*4warps*8subs = 192 x-cols, 190 y-rows, 4 batches
    je_lane_kernel<<<grd, blk>>>((const float*)d_in[0], (float*)d_out);
}